// round 15
// baseline (speedup 1.0000x reference)
#include <cuda_runtime.h>
#include <cuda_bf16.h>
#include <cstdint>
#include <math.h>

#define CB 2
#define CS2 2048
#define CS 1024
#define CC 1280
#define CNH 8
#define CHD 160
#define M_ALL 4096
#define HSZ 5242880
#define WSZ_C 1638400

#define STAGES 4
#define STG_B 20480          // bytes per stage (As 10240 + Bs 10240)
#define SMEMB (STAGES * STG_B)   // 81920

// flash smem layout (bytes)
#define FL_SQ 0              // 128x168 bf16 = 43008
#define FL_SK 43008          // 2 x (128x168 bf16) = 86016
#define FL_SV 129024         // 160x136 bf16 = 43520
#define FL_SP 172544         // 128x136 bf16 = 34816
#define FL_RS 207360         // 4x128 f32 = 2048
#define FL_SMEM 209408

typedef __nv_bfloat16 bf16;

// ---- scratch (static device globals: allocation-free) ----
__device__ float g_w[M_ALL];
__device__ bf16  g_hsb[HSZ];
__device__ bf16  g_wT[7 * CC * CC];
__device__ bf16  g_q[HSZ];
__device__ bf16  g_k[HSZ];
__device__ bf16  g_vt[HSZ];              // V transposed: (B, C, S2)
__device__ bf16  g_ao[HSZ];

// ======================================================================
// helpers
// ======================================================================
#define LDSM4(R, addr) \
    asm volatile("ldmatrix.sync.aligned.m8n8.x4.shared.b16 {%0,%1,%2,%3}, [%4];" \
        : "=r"((R)[0]), "=r"((R)[1]), "=r"((R)[2]), "=r"((R)[3]) : "r"(addr))

#define LDSM2(R, addr) \
    asm volatile("ldmatrix.sync.aligned.m8n8.x2.shared.b16 {%0,%1}, [%2];" \
        : "=r"((R)[0]), "=r"((R)[1]) : "r"(addr))

__device__ __forceinline__ void mma16816(float* c, const unsigned* a, unsigned b0, unsigned b1) {
    asm volatile(
        "mma.sync.aligned.m16n8k16.row.col.f32.bf16.bf16.f32 "
        "{%0,%1,%2,%3}, {%4,%5,%6,%7}, {%8,%9}, {%0,%1,%2,%3};"
        : "+f"(c[0]), "+f"(c[1]), "+f"(c[2]), "+f"(c[3])
        : "r"(a[0]), "r"(a[1]), "r"(a[2]), "r"(a[3]), "r"(b0), "r"(b1));
}

__device__ __forceinline__ void cpa(unsigned d, const bf16* s, int szb) {
    asm volatile("cp.async.cg.shared.global [%0], [%1], 16, %2;" :: "r"(d), "l"(s), "r"(szb));
}
__device__ __forceinline__ void cpcommit() { asm volatile("cp.async.commit_group;"); }
__device__ __forceinline__ void cpwait()   { asm volatile("cp.async.wait_group %0;" :: "n"(STAGES - 2)); }
__device__ __forceinline__ void cpwait1()  { asm volatile("cp.async.wait_group 1;" ::: "memory"); }

__device__ __forceinline__ float ex2f(float x) {
    float y; asm("ex2.approx.f32 %0, %1;" : "=f"(y) : "f"(x)); return y;
}

// ======================================================================
// prep: fused (hs fp32->bf16 + gate dot) AND weight transpose, one launch.
// ======================================================================
__global__ __launch_bounds__(256) void prep(
    const float* __restrict__ hs, const float* __restrict__ mask,
    const float* __restrict__ ww, const float* __restrict__ wb,
    const float* w0, const float* w1, const float* w2, const float* w3,
    const float* w4, const float* w5, const float* w6,
    bf16* __restrict__ hsb, float* __restrict__ wout, bf16* __restrict__ wT)
{
    __shared__ float t[32][33];
    const int z = blockIdx.x;
    const int tid = threadIdx.x;

    if (z < M_ALL) {
        const float2* h2 = (const float2*)(hs + (size_t)z * CC);
        const float2* w2p = (const float2*)ww;
        __nv_bfloat162* o2 = (__nv_bfloat162*)(hsb + (size_t)z * CC);
        float acc = 0.f;
        for (int i = tid; i < 640; i += 256) {
            float2 v = h2[i];
            float2 w = w2p[i];
            acc += v.x * w.x + v.y * w.y;
            o2[i] = __floats2bfloat162_rn(v.x, v.y);
        }
        #pragma unroll
        for (int o = 16; o; o >>= 1) acc += __shfl_xor_sync(0xffffffffu, acc, o);
        if ((tid & 31) == 0) t[0][tid >> 5] = acc;
        __syncthreads();
        if (tid == 0) {
            float tot = 0.f;
            #pragma unroll
            for (int i = 0; i < 8; ++i) tot += t[0][i];
            int b = z / CS2;
            int s = (z % CS2) % CS;
            float mval = mask[(size_t)b * 65536 + (size_t)(s / 32) * 8 * 256 + (size_t)(s % 32) * 8];
            float x = tot + mval * ww[CC] + wb[0];
            wout[z] = 1.f / (1.f + expf(-x));
        }
        return;
    }

    const float* srcs[7] = {w0, w1, w2, w3, w4, w5, w6};
    int idx = z - M_ALL;
    int wz = idx / 1600;
    int r  = idx - wz * 1600;
    int by = r / 40, bx = r - by * 40;
    const float* src = srcs[wz];
    bf16* dst = wT + (size_t)wz * CC * CC;
    int tx = tid & 31, ty = tid >> 5;
    int x0 = bx * 32, y0 = by * 32;
    #pragma unroll
    for (int j = 0; j < 4; ++j)
        t[ty + j * 8][tx] = src[(size_t)(y0 + ty + j * 8) * CC + x0 + tx];
    __syncthreads();
    #pragma unroll
    for (int j = 0; j < 4; ++j)
        dst[(size_t)(x0 + ty + j * 8) * CC + y0 + tx] =
            __float2bfloat16(t[tx][ty + j * 8]);
}

// ======================================================================
// gemm_core64: tile 128x64 single-B, k=32 x 4 stages (dual-core addressing).
// Warp grid 4m x 2n, warp tile 32x32. B stage rows 0..63 valid.
// ======================================================================
__device__ __forceinline__ void gemm_core64(
    const bf16* pA, const bf16* pB, int bpr, unsigned sbase, int tid,
    float R[2][4][4])
{
    const int warp = tid >> 5, lane = tid & 31;
    const int wm = warp >> 1, wn = warp & 1;
    const int row = tid >> 1;
    const int col = (tid & 1) << 4;

    unsigned dA = sbase + (unsigned)((row * 40 + col) * 2);
    unsigned dB = dA + 10240;

    #pragma unroll
    for (int i = 0; i < 2; ++i)
        #pragma unroll
        for (int j = 0; j < 4; ++j)
            #pragma unroll
            for (int k = 0; k < 4; ++k) R[i][j][k] = 0.f;

    #pragma unroll
    for (int s = 0; s < STAGES - 1; ++s) {
        unsigned o = s * STG_B;
        cpa(dA + o,      pA + s * 32,      16);
        cpa(dA + o + 16, pA + s * 32 + 8,  16);
        cpa(dB + o,      pB + s * 32,      bpr);
        cpa(dB + o + 16, pB + s * 32 + 8,  bpr);
        cpcommit();
    }
    cpwait();
    __syncthreads();

    const int g = lane >> 3, lr = lane & 7;
    unsigned aAddr = sbase + (unsigned)(((wm * 32 + (g & 1) * 8 + lr) * 40 + (g >> 1) * 8) * 2);
    unsigned bAddr = sbase + 10240u + (unsigned)(((wn * 32 + (g >> 1) * 8 + lr) * 40 + (g & 1) * 8) * 2);

    const int ktiles = 40;
    for (int t = 0; t < ktiles; ++t) {
        int nt = t + STAGES - 1;
        if (nt < ktiles) {
            unsigned o = (nt & (STAGES - 1)) * STG_B;
            cpa(dA + o,      pA + nt * 32,      16);
            cpa(dA + o + 16, pA + nt * 32 + 8,  16);
            cpa(dB + o,      pB + nt * 32,      bpr);
            cpa(dB + o + 16, pB + nt * 32 + 8,  bpr);
        }
        cpcommit();

        unsigned o = (t & (STAGES - 1)) * STG_B;
        #pragma unroll
        for (int kk = 0; kk < 2; ++kk) {
            unsigned a0[4], a1[4];
            LDSM4(a0, aAddr + o + kk * 32);
            LDSM4(a1, aAddr + o + 1280 + kk * 32);
            #pragma unroll
            for (int jj = 0; jj < 2; ++jj) {
                unsigned b[4];
                LDSM4(b, bAddr + o + jj * 1280 + kk * 32);
                mma16816(R[0][2 * jj],     a0, b[0], b[1]);
                mma16816(R[1][2 * jj],     a1, b[0], b[1]);
                mma16816(R[0][2 * jj + 1], a0, b[2], b[3]);
                mma16816(R[1][2 * jj + 1], a1, b[2], b[3]);
            }
        }
        cpwait();
        __syncthreads();
    }
}

// ======================================================================
// Dual-B core: tile 128x64, computes A@Wq and A@Wp simultaneously.
// ======================================================================
__device__ __forceinline__ void gemm_core_dual(
    const bf16* pA, const bf16* pB, unsigned sbase, int tid,
    float Rq[2][4][4], float Rp[2][4][4])
{
    const int warp = tid >> 5, lane = tid & 31;
    const int wm = warp >> 1, wn = warp & 1;
    const int row = tid >> 1;
    const int col = (tid & 1) << 4;

    unsigned dA = sbase + (unsigned)((row * 40 + col) * 2);
    unsigned dB = dA + 10240;

    #pragma unroll
    for (int i = 0; i < 2; ++i)
        #pragma unroll
        for (int j = 0; j < 4; ++j)
            #pragma unroll
            for (int k = 0; k < 4; ++k) { Rq[i][j][k] = 0.f; Rp[i][j][k] = 0.f; }

    #pragma unroll
    for (int s = 0; s < STAGES - 1; ++s) {
        unsigned o = s * STG_B;
        cpa(dA + o,      pA + s * 32,      16);
        cpa(dA + o + 16, pA + s * 32 + 8,  16);
        cpa(dB + o,      pB + s * 32,      16);
        cpa(dB + o + 16, pB + s * 32 + 8,  16);
        cpcommit();
    }
    cpwait();
    __syncthreads();

    const int g = lane >> 3, lr = lane & 7;
    unsigned aAddr = sbase + (unsigned)(((wm * 32 + (g & 1) * 8 + lr) * 40 + (g >> 1) * 8) * 2);
    unsigned bAddrQ = sbase + 10240u + (unsigned)(((wn * 32 + (g >> 1) * 8 + lr) * 40 + (g & 1) * 8) * 2);
    unsigned bAddrP = bAddrQ + 64u * 80u;

    const int ktiles = 40;
    for (int t = 0; t < ktiles; ++t) {
        int nt = t + STAGES - 1;
        if (nt < ktiles) {
            unsigned o = (nt & (STAGES - 1)) * STG_B;
            cpa(dA + o,      pA + nt * 32,      16);
            cpa(dA + o + 16, pA + nt * 32 + 8,  16);
            cpa(dB + o,      pB + nt * 32,      16);
            cpa(dB + o + 16, pB + nt * 32 + 8,  16);
        }
        cpcommit();

        unsigned o = (t & (STAGES - 1)) * STG_B;
        #pragma unroll
        for (int kk = 0; kk < 2; ++kk) {
            unsigned a0[4], a1[4];
            LDSM4(a0, aAddr + o + kk * 32);
            LDSM4(a1, aAddr + o + 1280 + kk * 32);
            #pragma unroll
            for (int jj = 0; jj < 2; ++jj) {
                unsigned b[4];
                LDSM4(b, bAddrQ + o + jj * 1280 + kk * 32);
                mma16816(Rq[0][2 * jj],     a0, b[0], b[1]);
                mma16816(Rq[1][2 * jj],     a1, b[0], b[1]);
                mma16816(Rq[0][2 * jj + 1], a0, b[2], b[3]);
                mma16816(Rq[1][2 * jj + 1], a1, b[2], b[3]);
                LDSM4(b, bAddrP + o + jj * 1280 + kk * 32);
                mma16816(Rp[0][2 * jj],     a0, b[0], b[1]);
                mma16816(Rp[1][2 * jj],     a1, b[0], b[1]);
                mma16816(Rp[0][2 * jj + 1], a0, b[2], b[3]);
                mma16816(Rp[1][2 * jj + 1], a1, b[2], b[3]);
            }
        }
        cpwait();
        __syncthreads();
    }
}

// ======================================================================
// Merged projection kernel, all 64-wide n-tiles. grid (20, 96).
//   y in [0,32):  dual-Q fused gate (m-tile = y)
//   y in [32,64): K
//   y in [64,96): V transposed
// ======================================================================
__global__ __launch_bounds__(256, 2) void proj_all(
    const bf16* __restrict__ HSB, const bf16* __restrict__ WT,
    const float* __restrict__ W, float qsc,
    bf16* __restrict__ Qo, bf16* __restrict__ Kb, bf16* __restrict__ Vt)
{
    extern __shared__ __align__(16) bf16 smg[];
    const int y = blockIdx.y;
    const int tid = threadIdx.x;
    const int warp = tid >> 5, lane = tid & 31;
    const int wm = warp >> 1, wn = warp & 1;
    const int gr = lane >> 2, gc = (lane & 3) * 2;
    const int n0 = blockIdx.x * 64;
    const int row = tid >> 1;
    const int col = (tid & 1) << 4;
    unsigned sbase = (unsigned)__cvta_generic_to_shared(smg);

    if (y < 32) {
        // ---- dual-Q with fused gate ----
        int my = y;
        const bf16* pA = HSB + (size_t)my * 128 * CC + (size_t)row * CC + col;
        const bf16* pB;
        if (row < 64) pB = WT + (size_t)(n0 + row) * CC + col;
        else          pB = WT + WSZ_C + (size_t)(n0 + row - 64) * CC + col;

        float Rq[2][4][4], Rp[2][4][4];
        gemm_core_dual(pA, pB, sbase, tid, Rq, Rp);

        bf16* C = Qo + (size_t)my * 128 * CC;
        #pragma unroll
        for (int mi = 0; mi < 2; ++mi)
            #pragma unroll
            for (int hh = 0; hh < 2; ++hh) {
                int m = wm * 32 + mi * 16 + gr + hh * 8;
                float wv = W[my * 128 + m];
                float iw = 1.f - wv;
                #pragma unroll
                for (int jj = 0; jj < 4; ++jj) {
                    int n = n0 + wn * 32 + jj * 8 + gc;
                    float v0 = (Rq[mi][jj][2 * hh]     * wv + Rp[mi][jj][2 * hh]     * iw) * qsc;
                    float v1 = (Rq[mi][jj][2 * hh + 1] * wv + Rp[mi][jj][2 * hh + 1] * iw) * qsc;
                    *(__nv_bfloat162*)(C + (size_t)m * CC + n) = __floats2bfloat162_rn(v0, v1);
                }
            }
        return;
    }

    // ---- K / V regions, 128x64 single-B ----
    int u = y & 31;
    int bh = u >> 3, my = u & 7;
    int b = bh >> 1, half = bh & 1;
    const bf16* A = HSB + (size_t)b * (CS2 * CC) + (size_t)half * CS * CC + (size_t)my * 128 * CC;
    const bf16* B;
    bf16* C;
    int ldc;
    bool transo;
    if (y < 64) {
        B = WT + (size_t)(2 + half) * WSZ_C;
        C = Kb + (size_t)b * (CS2 * CC) + (size_t)half * CS * CC + (size_t)my * 128 * CC;
        ldc = CC;
        transo = false;
    } else {
        B = WT + (size_t)(4 + half) * WSZ_C;
        C = Vt + (size_t)b * (CC * CS2) + (size_t)half * CS + (size_t)my * 128;
        ldc = CS2;
        transo = true;
    }

    const bf16* pA = A + (size_t)row * CC + col;
    int brow = (row < 64) ? row : 0;
    int bpr  = (row < 64) ? 16 : 0;
    const bf16* pB = B + (size_t)(n0 + brow) * CC + col;

    float R[2][4][4];
    gemm_core64(pA, pB, bpr, sbase, tid, R);

    if (!transo) {
        #pragma unroll
        for (int mi = 0; mi < 2; ++mi)
            #pragma unroll
            for (int jj = 0; jj < 4; ++jj) {
                int n = n0 + wn * 32 + jj * 8 + gc;
                #pragma unroll
                for (int h = 0; h < 2; ++h) {
                    int m = wm * 32 + mi * 16 + gr + h * 8;
                    __nv_bfloat162 p = __floats2bfloat162_rn(R[mi][jj][2 * h],
                                                             R[mi][jj][2 * h + 1]);
                    *(__nv_bfloat162*)(C + (size_t)m * ldc + n) = p;
                }
            }
    } else {
        #pragma unroll
        for (int mi = 0; mi < 2; ++mi)
            #pragma unroll
            for (int jj = 0; jj < 4; ++jj) {
                int n = n0 + wn * 32 + jj * 8 + gc;
                #pragma unroll
                for (int h = 0; h < 2; ++h) {
                    int m = wm * 32 + mi * 16 + gr + h * 8;
                    C[(size_t)n * ldc + m]       = __float2bfloat16(R[mi][jj][2 * h]);
                    C[(size_t)(n + 1) * ldc + m] = __float2bfloat16(R[mi][jj][2 * h + 1]);
                }
            }
    }
}

// ======================================================================
// out-projection GEMM 128x64 tiles, fused bias + residual (fp32 out).
// grid (20, 32).
// ======================================================================
__global__ __launch_bounds__(256, 2) void ogemm(
    const bf16* __restrict__ A, const bf16* __restrict__ B, float* __restrict__ Cf,
    const float* __restrict__ bias, const float* __restrict__ resid)
{
    extern __shared__ __align__(16) bf16 smg[];
    const int tid = threadIdx.x;
    const int m0 = blockIdx.y * 128, n0 = blockIdx.x * 64;
    const int warp = tid >> 5, lane = tid & 31;
    const int wm = warp >> 1, wn = warp & 1;
    const int row = tid >> 1;
    const int col = (tid & 1) << 4;

    const bf16* pA = A + (size_t)(m0 + row) * CC + col;
    int brow = (row < 64) ? row : 0;
    int bpr  = (row < 64) ? 16 : 0;
    const bf16* pB = B + (size_t)(n0 + brow) * CC + col;

    unsigned sbase = (unsigned)__cvta_generic_to_shared(smg);
    float R[2][4][4];
    gemm_core64(pA, pB, bpr, sbase, tid, R);

    const int gr = lane >> 2, gc = (lane & 3) * 2;
    #pragma unroll
    for (int mi = 0; mi < 2; ++mi)
        #pragma unroll
        for (int jj = 0; jj < 4; ++jj) {
            int n = n0 + wn * 32 + jj * 8 + gc;
            #pragma unroll
            for (int h = 0; h < 2; ++h) {
                int m = m0 + wm * 32 + mi * 16 + gr + h * 8;
                float v0 = R[mi][jj][2 * h]     + bias[n]     + resid[(size_t)m * CC + n];
                float v1 = R[mi][jj][2 * h + 1] + bias[n + 1] + resid[(size_t)m * CC + n + 1];
                *(float2*)(Cf + (size_t)m * CC + n) = make_float2(v0, v1);
            }
        }
}

// ======================================================================
// Fused flash attention, static-max variant (R8, known good).
// ======================================================================
__global__ __launch_bounds__(512, 1) void flash(
    const bf16* __restrict__ Qg, const bf16* __restrict__ Kg,
    const bf16* __restrict__ Vg, bf16* __restrict__ Og)
{
    extern __shared__ __align__(16) char sm[];
    unsigned sb = (unsigned)__cvta_generic_to_shared(sm);
    const int tid = threadIdx.x;
    const int warp = tid >> 5, lane = tid & 31;
    const int wm = warp >> 2, wn = warp & 3;
    const int g = lane >> 3, lr = lane & 7;
    const int q2 = lane & 3, gr = lane >> 2;
    const int b = blockIdx.y >> 3, h = blockIdx.y & 7;
    const int qt = blockIdx.x;

    const bf16* Qp = Qg + (size_t)b * CS2 * CC + (size_t)qt * 128 * CC + h * CHD;
    const bf16* Kp = Kg + (size_t)b * CS2 * CC + h * CHD;
    const bf16* Vp = Vg + (size_t)b * CC * CS2 + (size_t)h * CHD * CS2;

    #pragma unroll
    for (int i = 0; i < 5; ++i) {
        int c = tid + (i << 9); int row = c / 20, c16 = c % 20;
        cpa(sb + FL_SQ + row * 336 + c16 * 16, Qp + (size_t)row * CC + c16 * 8, 16);
    }
    cpcommit();
    #pragma unroll
    for (int i = 0; i < 5; ++i) {
        int c = tid + (i << 9); int row = c / 20, c16 = c % 20;
        cpa(sb + FL_SK + row * 336 + c16 * 16, Kp + (size_t)row * CC + c16 * 8, 16);
    }
    cpcommit();
    #pragma unroll
    for (int i = 0; i < 5; ++i) {
        int c = tid + (i << 9); int row = c / 16, c16 = c % 16;
        cpa(sb + FL_SV + row * 272 + c16 * 16, Vp + (size_t)row * CS2 + c16 * 8, 16);
    }
    cpcommit();

    float O[2][5][4];
    #pragma unroll
    for (int i = 0; i < 2; ++i)
        #pragma unroll
        for (int j = 0; j < 5; ++j)
            #pragma unroll
            for (int k = 0; k < 4; ++k) O[i][j][k] = 0.f;
    float lsum[2][2] = {{0.f, 0.f}, {0.f, 0.f}};

    unsigned aQ  = sb + FL_SQ + (unsigned)(((wm * 32 + (g & 1) * 8 + lr) * 168 + (g >> 1) * 8) * 2);
    unsigned aP  = sb + FL_SP + (unsigned)(((wm * 32 + (g & 1) * 8 + lr) * 136 + (g >> 1) * 8) * 2);
    unsigned bVa = sb + FL_SV + (unsigned)(((wn * 40 + (g >> 1) * 8 + lr) * 136 + (g & 1) * 8) * 2);
    unsigned bV2 = sb + FL_SV + (unsigned)(((wn * 40 + 32 + lr) * 136 + ((lane >> 3) & 1) * 8) * 2);
    unsigned bKl = sb + FL_SK + (unsigned)(((wn * 32 + (g >> 1) * 8 + lr) * 168 + (g & 1) * 8) * 2);

    bf16* sPp = (bf16*)(sm + FL_SP);

    for (int t = 0; t < 16; ++t) {
        cpwait1();
        __syncthreads();
        if (t < 15) {
            unsigned kb = sb + FL_SK + (unsigned)(((t + 1) & 1) * 43008);
            const bf16* src = Kp + (size_t)(t + 1) * 128 * CC;
            #pragma unroll
            for (int i = 0; i < 5; ++i) {
                int c = tid + (i << 9); int row = c / 20, c16 = c % 20;
                cpa(kb + row * 336 + c16 * 16, src + (size_t)row * CC + c16 * 8, 16);
            }
        }
        cpcommit();

        float S[2][4][4];
        #pragma unroll
        for (int i = 0; i < 2; ++i)
            #pragma unroll
            for (int j = 0; j < 4; ++j)
                #pragma unroll
                for (int k = 0; k < 4; ++k) S[i][j][k] = 0.f;
        unsigned bK = bKl + (unsigned)((t & 1) * 43008);
        #pragma unroll
        for (int kk = 0; kk < 10; ++kk) {
            unsigned a0[4], a1[4], bb[4];
            LDSM4(a0, aQ + kk * 32);
            LDSM4(a1, aQ + kk * 32 + 5376);
            LDSM4(bb, bK + kk * 32);
            mma16816(S[0][0], a0, bb[0], bb[1]);
            mma16816(S[0][1], a0, bb[2], bb[3]);
            mma16816(S[1][0], a1, bb[0], bb[1]);
            mma16816(S[1][1], a1, bb[2], bb[3]);
            LDSM4(bb, bK + kk * 32 + 5376);
            mma16816(S[0][2], a0, bb[0], bb[1]);
            mma16816(S[0][3], a0, bb[2], bb[3]);
            mma16816(S[1][2], a1, bb[0], bb[1]);
            mma16816(S[1][3], a1, bb[2], bb[3]);
        }

        #pragma unroll
        for (int mi = 0; mi < 2; ++mi)
            #pragma unroll
            for (int jj = 0; jj < 4; ++jj)
                #pragma unroll
                for (int hh = 0; hh < 2; ++hh) {
                    float p0 = ex2f(S[mi][jj][2 * hh]);
                    float p1 = ex2f(S[mi][jj][2 * hh + 1]);
                    lsum[mi][hh] += p0 + p1;
                    int prow = wm * 32 + mi * 16 + hh * 8 + gr;
                    int pcol = wn * 32 + jj * 8 + q2 * 2;
                    *(__nv_bfloat162*)(sPp + prow * 136 + pcol) = __floats2bfloat162_rn(p0, p1);
                }

        cpwait1();
        __syncthreads();

        #pragma unroll
        for (int kk = 0; kk < 8; ++kk) {
            unsigned a0[4], a1[4], bb[4], b2[2];
            LDSM4(a0, aP + kk * 32);
            LDSM4(a1, aP + kk * 32 + 4352);
            LDSM4(bb, bVa + kk * 32);
            mma16816(O[0][0], a0, bb[0], bb[1]);
            mma16816(O[0][1], a0, bb[2], bb[3]);
            mma16816(O[1][0], a1, bb[0], bb[1]);
            mma16816(O[1][1], a1, bb[2], bb[3]);
            LDSM4(bb, bVa + kk * 32 + 4352);
            mma16816(O[0][2], a0, bb[0], bb[1]);
            mma16816(O[0][3], a0, bb[2], bb[3]);
            mma16816(O[1][2], a1, bb[0], bb[1]);
            mma16816(O[1][3], a1, bb[2], bb[3]);
            LDSM2(b2, bV2 + kk * 32);
            mma16816(O[0][4], a0, b2[0], b2[1]);
            mma16816(O[1][4], a1, b2[0], b2[1]);
        }
        __syncthreads();
        if (t < 15) {
            const bf16* src = Vp + (size_t)(t + 1) * 128;
            #pragma unroll
            for (int i = 0; i < 5; ++i) {
                int c = tid + (i << 9); int row = c / 16, c16 = c % 16;
                cpa(sb + FL_SV + row * 272 + c16 * 16, src + (size_t)row * CS2 + c16 * 8, 16);
            }
            cpcommit();
        }
    }

    float* smRS = (float*)(sm + FL_RS);
    #pragma unroll
    for (int mi = 0; mi < 2; ++mi)
        #pragma unroll
        for (int hh = 0; hh < 2; ++hh) {
            float s = lsum[mi][hh];
            s += __shfl_xor_sync(0xffffffffu, s, 1);
            s += __shfl_xor_sync(0xffffffffu, s, 2);
            if (q2 == 0) smRS[wn * 128 + wm * 32 + mi * 16 + hh * 8 + gr] = s;
        }
    __syncthreads();
    float inv[2][2];
    #pragma unroll
    for (int mi = 0; mi < 2; ++mi)
        #pragma unroll
        for (int hh = 0; hh < 2; ++hh) {
            int r = wm * 32 + mi * 16 + hh * 8 + gr;
            float tot = smRS[r] + smRS[128 + r] + smRS[256 + r] + smRS[384 + r];
            inv[mi][hh] = 1.f / tot;
        }
    bf16* Ob = Og + (size_t)b * CS2 * CC + (size_t)qt * 128 * CC + h * CHD;
    #pragma unroll
    for (int mi = 0; mi < 2; ++mi)
        #pragma unroll
        for (int jj = 0; jj < 5; ++jj)
            #pragma unroll
            for (int hh = 0; hh < 2; ++hh) {
                int row = wm * 32 + mi * 16 + hh * 8 + gr;
                int col = wn * 40 + jj * 8 + q2 * 2;
                __nv_bfloat162 p = __floats2bfloat162_rn(O[mi][jj][2 * hh] * inv[mi][hh],
                                                         O[mi][jj][2 * hh + 1] * inv[mi][hh]);
                *(__nv_bfloat162*)(Ob + (size_t)row * CC + col) = p;
            }
}

// ======================================================================
// launch
// ======================================================================
template<typename T>
static T* symaddr(const void* s) {
    void* p = nullptr;
    cudaGetSymbolAddress(&p, s);
    return (T*)p;
}

extern "C" void kernel_launch(void* const* d_in, const int* in_sizes, int n_in,
                              void* d_out, int out_size)
{
    const float* hs       = (const float*)d_in[0];
    const float* src_mask = (const float*)d_in[1];
    const float* attn_wq  = (const float*)d_in[2];
    const float* attn_wk  = (const float*)d_in[3];
    const float* attn_wv  = (const float*)d_in[4];
    const float* out_w    = (const float*)d_in[5];
    const float* out_b    = (const float*)d_in[6];
    const float* proc_wq  = (const float*)d_in[7];
    const float* proc_wk  = (const float*)d_in[8];
    const float* proc_wv  = (const float*)d_in[9];
    const float* ww       = (const float*)d_in[10];
    const float* wb       = (const float*)d_in[11];
    float* out = (float*)d_out;

    float* W   = symaddr<float>(g_w);
    bf16*  HSB = symaddr<bf16>(g_hsb);
    bf16*  WT  = symaddr<bf16>(g_wT);
    bf16*  Q   = symaddr<bf16>(g_q);
    bf16*  Kb  = symaddr<bf16>(g_k);
    bf16*  Vt  = symaddr<bf16>(g_vt);
    bf16*  AO  = symaddr<bf16>(g_ao);

    const float qsc = (1.0f / sqrtf((float)CHD)) * 1.44269504f;

    cudaFuncSetAttribute(proj_all, cudaFuncAttributeMaxDynamicSharedMemorySize, SMEMB);
    cudaFuncSetAttribute(ogemm,    cudaFuncAttributeMaxDynamicSharedMemorySize, SMEMB);
    cudaFuncSetAttribute(flash,    cudaFuncAttributeMaxDynamicSharedMemorySize, FL_SMEM);

    // 0) fused prep: convert+gate AND weight transposes in one launch
    prep<<<M_ALL + 11200, 256>>>(hs, src_mask, ww, wb,
                                 attn_wq, proc_wq, attn_wk, proc_wk,
                                 attn_wv, proc_wv, out_w,
                                 HSB, W, WT);

    // 1) all projections (fused-gate Q, K, V), 64-wide n-tiles
    proj_all<<<dim3(20, 96), 256, SMEMB>>>(HSB, WT, W, qsc, Q, Kb, Vt);

    // 2) fused attention
    flash<<<dim3(16, 16), 512, FL_SMEM>>>(Q, Kb, Vt, AO);

    // 3) out = attn_out @ out_w + out_b + hidden, 64-wide n-tiles
    ogemm<<<dim3(20, 32), 256, SMEMB>>>(AO, WT + 6 * WSZ_C, out, out_b, hs);
}

// round 16
// speedup vs baseline: 1.0652x; 1.0652x over previous
#include <cuda_runtime.h>
#include <cuda_bf16.h>
#include <cstdint>
#include <math.h>

#define CB 2
#define CS2 2048
#define CS 1024
#define CC 1280
#define CNH 8
#define CHD 160
#define M_ALL 4096
#define HSZ 5242880
#define WSZ_C 1638400

#define STAGES 4
#define STG_B 20480          // bytes per stage (As 10240 + Bs 10240)
#define SMEMB (STAGES * STG_B)   // 81920

// flash smem layout (bytes)
#define FL_SQ 0              // 128x168 bf16 = 43008
#define FL_SK 43008          // 2 x (128x168 bf16) = 86016
#define FL_SV 129024         // 160x136 bf16 = 43520
#define FL_SP 172544         // 128x136 bf16 = 34816
#define FL_RS 207360         // 4x128 f32 = 2048
#define FL_SMEM 209408

typedef __nv_bfloat16 bf16;

// ---- scratch (static device globals: allocation-free) ----
__device__ float g_w[M_ALL];
__device__ bf16  g_hsb[HSZ];
__device__ bf16  g_wT[7 * CC * CC];
__device__ bf16  g_q[HSZ];
__device__ bf16  g_k[HSZ];
__device__ bf16  g_vt[HSZ];              // V transposed: (B, C, S2)
__device__ bf16  g_ao[HSZ];

// ======================================================================
// helpers
// ======================================================================
#define LDSM4(R, addr) \
    asm volatile("ldmatrix.sync.aligned.m8n8.x4.shared.b16 {%0,%1,%2,%3}, [%4];" \
        : "=r"((R)[0]), "=r"((R)[1]), "=r"((R)[2]), "=r"((R)[3]) : "r"(addr))

#define LDSM2(R, addr) \
    asm volatile("ldmatrix.sync.aligned.m8n8.x2.shared.b16 {%0,%1}, [%2];" \
        : "=r"((R)[0]), "=r"((R)[1]) : "r"(addr))

__device__ __forceinline__ void mma16816(float* c, const unsigned* a, unsigned b0, unsigned b1) {
    asm volatile(
        "mma.sync.aligned.m16n8k16.row.col.f32.bf16.bf16.f32 "
        "{%0,%1,%2,%3}, {%4,%5,%6,%7}, {%8,%9}, {%0,%1,%2,%3};"
        : "+f"(c[0]), "+f"(c[1]), "+f"(c[2]), "+f"(c[3])
        : "r"(a[0]), "r"(a[1]), "r"(a[2]), "r"(a[3]), "r"(b0), "r"(b1));
}

__device__ __forceinline__ void cpa(unsigned d, const bf16* s, int szb) {
    asm volatile("cp.async.cg.shared.global [%0], [%1], 16, %2;" :: "r"(d), "l"(s), "r"(szb));
}
__device__ __forceinline__ void cpcommit() { asm volatile("cp.async.commit_group;"); }
__device__ __forceinline__ void cpwait()   { asm volatile("cp.async.wait_group %0;" :: "n"(STAGES - 2)); }
__device__ __forceinline__ void cpwait1()  { asm volatile("cp.async.wait_group 1;" ::: "memory"); }

__device__ __forceinline__ float ex2f(float x) {
    float y; asm("ex2.approx.f32 %0, %1;" : "=f"(y) : "f"(x)); return y;
}

// ======================================================================
// prep: fused (hs fp32->bf16 + gate dot) AND weight transpose, one launch.
// blocks [0, 4096): one hs row each (gate + convert)
// blocks [4096, 15296): weight transpose tiles (7 x 40 x 40)
// ======================================================================
__global__ __launch_bounds__(256) void prep(
    const float* __restrict__ hs, const float* __restrict__ mask,
    const float* __restrict__ ww, const float* __restrict__ wb,
    const float* w0, const float* w1, const float* w2, const float* w3,
    const float* w4, const float* w5, const float* w6,
    bf16* __restrict__ hsb, float* __restrict__ wout, bf16* __restrict__ wT)
{
    __shared__ float t[32][33];
    const int z = blockIdx.x;
    const int tid = threadIdx.x;

    if (z < M_ALL) {
        const float2* h2 = (const float2*)(hs + (size_t)z * CC);
        const float2* w2p = (const float2*)ww;
        __nv_bfloat162* o2 = (__nv_bfloat162*)(hsb + (size_t)z * CC);
        float acc = 0.f;
        for (int i = tid; i < 640; i += 256) {
            float2 v = h2[i];
            float2 w = w2p[i];
            acc += v.x * w.x + v.y * w.y;
            o2[i] = __floats2bfloat162_rn(v.x, v.y);
        }
        #pragma unroll
        for (int o = 16; o; o >>= 1) acc += __shfl_xor_sync(0xffffffffu, acc, o);
        if ((tid & 31) == 0) t[0][tid >> 5] = acc;
        __syncthreads();
        if (tid == 0) {
            float tot = 0.f;
            #pragma unroll
            for (int i = 0; i < 8; ++i) tot += t[0][i];
            int b = z / CS2;
            int s = (z % CS2) % CS;
            float mval = mask[(size_t)b * 65536 + (size_t)(s / 32) * 8 * 256 + (size_t)(s % 32) * 8];
            float x = tot + mval * ww[CC] + wb[0];
            wout[z] = 1.f / (1.f + expf(-x));
        }
        return;
    }

    const float* srcs[7] = {w0, w1, w2, w3, w4, w5, w6};
    int idx = z - M_ALL;
    int wz = idx / 1600;
    int r  = idx - wz * 1600;
    int by = r / 40, bx = r - by * 40;
    const float* src = srcs[wz];
    bf16* dst = wT + (size_t)wz * CC * CC;
    int tx = tid & 31, ty = tid >> 5;       // 32 x 8
    int x0 = bx * 32, y0 = by * 32;
    #pragma unroll
    for (int j = 0; j < 4; ++j)
        t[ty + j * 8][tx] = src[(size_t)(y0 + ty + j * 8) * CC + x0 + tx];
    __syncthreads();
    #pragma unroll
    for (int j = 0; j < 4; ++j)
        dst[(size_t)(x0 + ty + j * 8) * CC + y0 + tx] =
            __float2bfloat16(t[tx][ty + j * 8]);
}

// ======================================================================
// R8-proven 4-stage k=32 pipeline core (single B, 128x128 tile).
// ======================================================================
struct GemmAcc { float a[2][8][4]; };

__device__ __forceinline__ void gemm_core(
    const bf16* pA, const bf16* pB, unsigned sbase, int tid, GemmAcc& R)
{
    const int warp = tid >> 5, lane = tid & 31;
    const int wm = warp >> 1, wn = warp & 1;
    const int row = tid >> 1;
    const int col = (tid & 1) << 4;

    unsigned dA = sbase + (unsigned)((row * 40 + col) * 2);
    unsigned dB = dA + 10240;

    #pragma unroll
    for (int i = 0; i < 2; ++i)
        #pragma unroll
        for (int j = 0; j < 8; ++j)
            #pragma unroll
            for (int k = 0; k < 4; ++k) R.a[i][j][k] = 0.f;

    #pragma unroll
    for (int s = 0; s < STAGES - 1; ++s) {
        unsigned o = s * STG_B;
        cpa(dA + o,      pA + s * 32,      16);
        cpa(dA + o + 16, pA + s * 32 + 8,  16);
        cpa(dB + o,      pB + s * 32,      16);
        cpa(dB + o + 16, pB + s * 32 + 8,  16);
        cpcommit();
    }
    cpwait();
    __syncthreads();

    const int g = lane >> 3, lr = lane & 7;
    unsigned aAddr = sbase + (unsigned)(((wm * 32 + (g & 1) * 8 + lr) * 40 + (g >> 1) * 8) * 2);
    unsigned bAddr = sbase + 10240u + (unsigned)(((wn * 64 + (g >> 1) * 8 + lr) * 40 + (g & 1) * 8) * 2);

    const int ktiles = 40;
    for (int t = 0; t < ktiles; ++t) {
        int nt = t + STAGES - 1;
        if (nt < ktiles) {
            unsigned o = (nt & (STAGES - 1)) * STG_B;
            cpa(dA + o,      pA + nt * 32,      16);
            cpa(dA + o + 16, pA + nt * 32 + 8,  16);
            cpa(dB + o,      pB + nt * 32,      16);
            cpa(dB + o + 16, pB + nt * 32 + 8,  16);
        }
        cpcommit();

        unsigned o = (t & (STAGES - 1)) * STG_B;
        #pragma unroll
        for (int kk = 0; kk < 2; ++kk) {
            unsigned a0[4], a1[4];
            LDSM4(a0, aAddr + o + kk * 32);
            LDSM4(a1, aAddr + o + 1280 + kk * 32);
            #pragma unroll
            for (int jj = 0; jj < 4; ++jj) {
                unsigned b[4];
                LDSM4(b, bAddr + o + jj * 1280 + kk * 32);
                mma16816(R.a[0][2 * jj],     a0, b[0], b[1]);
                mma16816(R.a[1][2 * jj],     a1, b[0], b[1]);
                mma16816(R.a[0][2 * jj + 1], a0, b[2], b[3]);
                mma16816(R.a[1][2 * jj + 1], a1, b[2], b[3]);
            }
        }
        cpwait();
        __syncthreads();
    }
}

// ======================================================================
// Dual-B core: tile 128x64, computes A@Wq and A@Wp simultaneously.
// ======================================================================
__device__ __forceinline__ void gemm_core_dual(
    const bf16* pA, const bf16* pB, unsigned sbase, int tid,
    float Rq[2][4][4], float Rp[2][4][4])
{
    const int warp = tid >> 5, lane = tid & 31;
    const int wm = warp >> 1, wn = warp & 1;
    const int row = tid >> 1;
    const int col = (tid & 1) << 4;

    unsigned dA = sbase + (unsigned)((row * 40 + col) * 2);
    unsigned dB = dA + 10240;

    #pragma unroll
    for (int i = 0; i < 2; ++i)
        #pragma unroll
        for (int j = 0; j < 4; ++j)
            #pragma unroll
            for (int k = 0; k < 4; ++k) { Rq[i][j][k] = 0.f; Rp[i][j][k] = 0.f; }

    #pragma unroll
    for (int s = 0; s < STAGES - 1; ++s) {
        unsigned o = s * STG_B;
        cpa(dA + o,      pA + s * 32,      16);
        cpa(dA + o + 16, pA + s * 32 + 8,  16);
        cpa(dB + o,      pB + s * 32,      16);
        cpa(dB + o + 16, pB + s * 32 + 8,  16);
        cpcommit();
    }
    cpwait();
    __syncthreads();

    const int g = lane >> 3, lr = lane & 7;
    unsigned aAddr = sbase + (unsigned)(((wm * 32 + (g & 1) * 8 + lr) * 40 + (g >> 1) * 8) * 2);
    unsigned bAddrQ = sbase + 10240u + (unsigned)(((wn * 32 + (g >> 1) * 8 + lr) * 40 + (g & 1) * 8) * 2);
    unsigned bAddrP = bAddrQ + 64u * 80u;

    const int ktiles = 40;
    for (int t = 0; t < ktiles; ++t) {
        int nt = t + STAGES - 1;
        if (nt < ktiles) {
            unsigned o = (nt & (STAGES - 1)) * STG_B;
            cpa(dA + o,      pA + nt * 32,      16);
            cpa(dA + o + 16, pA + nt * 32 + 8,  16);
            cpa(dB + o,      pB + nt * 32,      16);
            cpa(dB + o + 16, pB + nt * 32 + 8,  16);
        }
        cpcommit();

        unsigned o = (t & (STAGES - 1)) * STG_B;
        #pragma unroll
        for (int kk = 0; kk < 2; ++kk) {
            unsigned a0[4], a1[4];
            LDSM4(a0, aAddr + o + kk * 32);
            LDSM4(a1, aAddr + o + 1280 + kk * 32);
            #pragma unroll
            for (int jj = 0; jj < 2; ++jj) {
                unsigned b[4];
                LDSM4(b, bAddrQ + o + jj * 1280 + kk * 32);
                mma16816(Rq[0][2 * jj],     a0, b[0], b[1]);
                mma16816(Rq[1][2 * jj],     a1, b[0], b[1]);
                mma16816(Rq[0][2 * jj + 1], a0, b[2], b[3]);
                mma16816(Rq[1][2 * jj + 1], a1, b[2], b[3]);
                LDSM4(b, bAddrP + o + jj * 1280 + kk * 32);
                mma16816(Rp[0][2 * jj],     a0, b[0], b[1]);
                mma16816(Rp[1][2 * jj],     a1, b[0], b[1]);
                mma16816(Rp[0][2 * jj + 1], a0, b[2], b[3]);
                mma16816(Rp[1][2 * jj + 1], a1, b[2], b[3]);
            }
        }
        cpwait();
        __syncthreads();
    }
}

// ======================================================================
// Merged projection kernel: y<64 dual-Q (128x64, fused gate), else K/V.
// grid (10, 128).
// ======================================================================
__global__ __launch_bounds__(256, 2) void proj_all(
    const bf16* __restrict__ HSB, const bf16* __restrict__ WT,
    const float* __restrict__ W, float qsc,
    bf16* __restrict__ Qo, bf16* __restrict__ Kb, bf16* __restrict__ Vt)
{
    extern __shared__ __align__(16) bf16 smg[];
    const int y = blockIdx.y;
    const int tid = threadIdx.x;
    const int warp = tid >> 5, lane = tid & 31;
    const int wm = warp >> 1, wn = warp & 1;
    const int gr = lane >> 2, gc = (lane & 3) * 2;
    unsigned sbase = (unsigned)__cvta_generic_to_shared(smg);

    if (y < 64) {
        int my = y >> 1;
        int n0 = ((y & 1) * 10 + blockIdx.x) * 64;
        const bf16* A = HSB + (size_t)my * 128 * CC;
        const int row = tid >> 1;
        const bf16* pA = A + (size_t)row * CC + ((tid & 1) << 4);
        const bf16* pB;
        if (row < 64) pB = WT + (size_t)(n0 + row) * CC + ((tid & 1) << 4);
        else          pB = WT + WSZ_C + (size_t)(n0 + row - 64) * CC + ((tid & 1) << 4);

        float Rq[2][4][4], Rp[2][4][4];
        gemm_core_dual(pA, pB, sbase, tid, Rq, Rp);

        bf16* C = Qo + (size_t)my * 128 * CC;
        #pragma unroll
        for (int mi = 0; mi < 2; ++mi)
            #pragma unroll
            for (int hh = 0; hh < 2; ++hh) {
                int m = wm * 32 + mi * 16 + gr + hh * 8;
                float wv = W[my * 128 + m];
                float iw = 1.f - wv;
                #pragma unroll
                for (int jj = 0; jj < 4; ++jj) {
                    int n = n0 + wn * 32 + jj * 8 + gc;
                    float v0 = (Rq[mi][jj][2 * hh]     * wv + Rp[mi][jj][2 * hh]     * iw) * qsc;
                    float v1 = (Rq[mi][jj][2 * hh + 1] * wv + Rp[mi][jj][2 * hh + 1] * iw) * qsc;
                    *(__nv_bfloat162*)(C + (size_t)m * CC + n) = __floats2bfloat162_rn(v0, v1);
                }
            }
        return;
    }

    const bf16* A;
    const bf16* B;
    bf16* C;
    int ldc;
    bool transo = false;
    {
        int u = y & 31;
        int bh = u >> 3, my = u & 7;
        int b = bh >> 1, half = bh & 1;
        A = HSB + (size_t)b * (CS2 * CC) + (size_t)half * CS * CC + (size_t)my * 128 * CC;
        if (y < 96) {
            B = WT + (size_t)(2 + half) * WSZ_C;
            C = Kb + (size_t)b * (CS2 * CC) + (size_t)half * CS * CC + (size_t)my * 128 * CC;
            ldc = CC;
        } else {
            B = WT + (size_t)(4 + half) * WSZ_C;
            C = Vt + (size_t)b * (CC * CS2) + (size_t)half * CS + (size_t)my * 128;
            ldc = CS2;
            transo = true;
        }
    }

    const int n0 = blockIdx.x * 128;
    const bf16* pA = A + (size_t)(tid >> 1) * CC + ((tid & 1) << 4);
    const bf16* pB = B + (size_t)(n0 + (tid >> 1)) * CC + ((tid & 1) << 4);

    GemmAcc R;
    gemm_core(pA, pB, sbase, tid, R);

    if (!transo) {
        #pragma unroll
        for (int mi = 0; mi < 2; ++mi)
            #pragma unroll
            for (int jj = 0; jj < 8; ++jj) {
                int n = n0 + wn * 64 + jj * 8 + gc;
                #pragma unroll
                for (int h = 0; h < 2; ++h) {
                    int m = wm * 32 + mi * 16 + gr + h * 8;
                    __nv_bfloat162 p = __floats2bfloat162_rn(R.a[mi][jj][2 * h],
                                                             R.a[mi][jj][2 * h + 1]);
                    *(__nv_bfloat162*)(C + (size_t)m * ldc + n) = p;
                }
            }
    } else {
        #pragma unroll
        for (int mi = 0; mi < 2; ++mi)
            #pragma unroll
            for (int jj = 0; jj < 8; ++jj) {
                int n = n0 + wn * 64 + jj * 8 + gc;
                #pragma unroll
                for (int h = 0; h < 2; ++h) {
                    int m = wm * 32 + mi * 16 + gr + h * 8;
                    C[(size_t)n * ldc + m]       = __float2bfloat16(R.a[mi][jj][2 * h]);
                    C[(size_t)(n + 1) * ldc + m] = __float2bfloat16(R.a[mi][jj][2 * h + 1]);
                }
            }
    }
}

// ======================================================================
// out-projection GEMM with fused bias + residual (fp32 out). grid (10, 32).
// ======================================================================
__global__ __launch_bounds__(256, 2) void ogemm(
    const bf16* __restrict__ A, const bf16* __restrict__ B, float* __restrict__ Cf,
    const float* __restrict__ bias, const float* __restrict__ resid)
{
    extern __shared__ __align__(16) bf16 smg[];
    const int tid = threadIdx.x;
    const int m0 = blockIdx.y * 128, n0 = blockIdx.x * 128;
    const int warp = tid >> 5, lane = tid & 31;
    const int wm = warp >> 1, wn = warp & 1;

    const bf16* pA = A + (size_t)(m0 + (tid >> 1)) * CC + ((tid & 1) << 4);
    const bf16* pB = B + (size_t)(n0 + (tid >> 1)) * CC + ((tid & 1) << 4);

    unsigned sbase = (unsigned)__cvta_generic_to_shared(smg);
    GemmAcc R;
    gemm_core(pA, pB, sbase, tid, R);

    const int gr = lane >> 2, gc = (lane & 3) * 2;
    #pragma unroll
    for (int mi = 0; mi < 2; ++mi)
        #pragma unroll
        for (int jj = 0; jj < 8; ++jj) {
            int n = n0 + wn * 64 + jj * 8 + gc;
            #pragma unroll
            for (int h = 0; h < 2; ++h) {
                int m = m0 + wm * 32 + mi * 16 + gr + h * 8;
                float v0 = R.a[mi][jj][2 * h]     + bias[n]     + resid[(size_t)m * CC + n];
                float v1 = R.a[mi][jj][2 * h + 1] + bias[n + 1] + resid[(size_t)m * CC + n + 1];
                *(float2*)(Cf + (size_t)m * CC + n) = make_float2(v0, v1);
            }
        }
}

// ======================================================================
// Fused flash attention, static-max variant (R8, known good).
// ======================================================================
__global__ __launch_bounds__(512, 1) void flash(
    const bf16* __restrict__ Qg, const bf16* __restrict__ Kg,
    const bf16* __restrict__ Vg, bf16* __restrict__ Og)
{
    extern __shared__ __align__(16) char sm[];
    unsigned sb = (unsigned)__cvta_generic_to_shared(sm);
    const int tid = threadIdx.x;
    const int warp = tid >> 5, lane = tid & 31;
    const int wm = warp >> 2, wn = warp & 3;
    const int g = lane >> 3, lr = lane & 7;
    const int q2 = lane & 3, gr = lane >> 2;
    const int b = blockIdx.y >> 3, h = blockIdx.y & 7;
    const int qt = blockIdx.x;

    const bf16* Qp = Qg + (size_t)b * CS2 * CC + (size_t)qt * 128 * CC + h * CHD;
    const bf16* Kp = Kg + (size_t)b * CS2 * CC + h * CHD;
    const bf16* Vp = Vg + (size_t)b * CC * CS2 + (size_t)h * CHD * CS2;

    #pragma unroll
    for (int i = 0; i < 5; ++i) {
        int c = tid + (i << 9); int row = c / 20, c16 = c % 20;
        cpa(sb + FL_SQ + row * 336 + c16 * 16, Qp + (size_t)row * CC + c16 * 8, 16);
    }
    cpcommit();
    #pragma unroll
    for (int i = 0; i < 5; ++i) {
        int c = tid + (i << 9); int row = c / 20, c16 = c % 20;
        cpa(sb + FL_SK + row * 336 + c16 * 16, Kp + (size_t)row * CC + c16 * 8, 16);
    }
    cpcommit();
    #pragma unroll
    for (int i = 0; i < 5; ++i) {
        int c = tid + (i << 9); int row = c / 16, c16 = c % 16;
        cpa(sb + FL_SV + row * 272 + c16 * 16, Vp + (size_t)row * CS2 + c16 * 8, 16);
    }
    cpcommit();

    float O[2][5][4];
    #pragma unroll
    for (int i = 0; i < 2; ++i)
        #pragma unroll
        for (int j = 0; j < 5; ++j)
            #pragma unroll
            for (int k = 0; k < 4; ++k) O[i][j][k] = 0.f;
    float lsum[2][2] = {{0.f, 0.f}, {0.f, 0.f}};

    unsigned aQ  = sb + FL_SQ + (unsigned)(((wm * 32 + (g & 1) * 8 + lr) * 168 + (g >> 1) * 8) * 2);
    unsigned aP  = sb + FL_SP + (unsigned)(((wm * 32 + (g & 1) * 8 + lr) * 136 + (g >> 1) * 8) * 2);
    unsigned bVa = sb + FL_SV + (unsigned)(((wn * 40 + (g >> 1) * 8 + lr) * 136 + (g & 1) * 8) * 2);
    unsigned bV2 = sb + FL_SV + (unsigned)(((wn * 40 + 32 + lr) * 136 + ((lane >> 3) & 1) * 8) * 2);
    unsigned bKl = sb + FL_SK + (unsigned)(((wn * 32 + (g >> 1) * 8 + lr) * 168 + (g & 1) * 8) * 2);

    bf16* sPp = (bf16*)(sm + FL_SP);

    for (int t = 0; t < 16; ++t) {
        cpwait1();
        __syncthreads();
        if (t < 15) {
            unsigned kb = sb + FL_SK + (unsigned)(((t + 1) & 1) * 43008);
            const bf16* src = Kp + (size_t)(t + 1) * 128 * CC;
            #pragma unroll
            for (int i = 0; i < 5; ++i) {
                int c = tid + (i << 9); int row = c / 20, c16 = c % 20;
                cpa(kb + row * 336 + c16 * 16, src + (size_t)row * CC + c16 * 8, 16);
            }
        }
        cpcommit();

        float S[2][4][4];
        #pragma unroll
        for (int i = 0; i < 2; ++i)
            #pragma unroll
            for (int j = 0; j < 4; ++j)
                #pragma unroll
                for (int k = 0; k < 4; ++k) S[i][j][k] = 0.f;
        unsigned bK = bKl + (unsigned)((t & 1) * 43008);
        #pragma unroll
        for (int kk = 0; kk < 10; ++kk) {
            unsigned a0[4], a1[4], bb[4];
            LDSM4(a0, aQ + kk * 32);
            LDSM4(a1, aQ + kk * 32 + 5376);
            LDSM4(bb, bK + kk * 32);
            mma16816(S[0][0], a0, bb[0], bb[1]);
            mma16816(S[0][1], a0, bb[2], bb[3]);
            mma16816(S[1][0], a1, bb[0], bb[1]);
            mma16816(S[1][1], a1, bb[2], bb[3]);
            LDSM4(bb, bK + kk * 32 + 5376);
            mma16816(S[0][2], a0, bb[0], bb[1]);
            mma16816(S[0][3], a0, bb[2], bb[3]);
            mma16816(S[1][2], a1, bb[0], bb[1]);
            mma16816(S[1][3], a1, bb[2], bb[3]);
        }

        #pragma unroll
        for (int mi = 0; mi < 2; ++mi)
            #pragma unroll
            for (int jj = 0; jj < 4; ++jj)
                #pragma unroll
                for (int hh = 0; hh < 2; ++hh) {
                    float p0 = ex2f(S[mi][jj][2 * hh]);
                    float p1 = ex2f(S[mi][jj][2 * hh + 1]);
                    lsum[mi][hh] += p0 + p1;
                    int prow = wm * 32 + mi * 16 + hh * 8 + gr;
                    int pcol = wn * 32 + jj * 8 + q2 * 2;
                    *(__nv_bfloat162*)(sPp + prow * 136 + pcol) = __floats2bfloat162_rn(p0, p1);
                }

        cpwait1();
        __syncthreads();

        #pragma unroll
        for (int kk = 0; kk < 8; ++kk) {
            unsigned a0[4], a1[4], bb[4], b2[2];
            LDSM4(a0, aP + kk * 32);
            LDSM4(a1, aP + kk * 32 + 4352);
            LDSM4(bb, bVa + kk * 32);
            mma16816(O[0][0], a0, bb[0], bb[1]);
            mma16816(O[0][1], a0, bb[2], bb[3]);
            mma16816(O[1][0], a1, bb[0], bb[1]);
            mma16816(O[1][1], a1, bb[2], bb[3]);
            LDSM4(bb, bVa + kk * 32 + 4352);
            mma16816(O[0][2], a0, bb[0], bb[1]);
            mma16816(O[0][3], a0, bb[2], bb[3]);
            mma16816(O[1][2], a1, bb[0], bb[1]);
            mma16816(O[1][3], a1, bb[2], bb[3]);
            LDSM2(b2, bV2 + kk * 32);
            mma16816(O[0][4], a0, b2[0], b2[1]);
            mma16816(O[1][4], a1, b2[0], b2[1]);
        }
        __syncthreads();
        if (t < 15) {
            const bf16* src = Vp + (size_t)(t + 1) * 128;
            #pragma unroll
            for (int i = 0; i < 5; ++i) {
                int c = tid + (i << 9); int row = c / 16, c16 = c % 16;
                cpa(sb + FL_SV + row * 272 + c16 * 16, src + (size_t)row * CS2 + c16 * 8, 16);
            }
            cpcommit();
        }
    }

    float* smRS = (float*)(sm + FL_RS);
    #pragma unroll
    for (int mi = 0; mi < 2; ++mi)
        #pragma unroll
        for (int hh = 0; hh < 2; ++hh) {
            float s = lsum[mi][hh];
            s += __shfl_xor_sync(0xffffffffu, s, 1);
            s += __shfl_xor_sync(0xffffffffu, s, 2);
            if (q2 == 0) smRS[wn * 128 + wm * 32 + mi * 16 + hh * 8 + gr] = s;
        }
    __syncthreads();
    float inv[2][2];
    #pragma unroll
    for (int mi = 0; mi < 2; ++mi)
        #pragma unroll
        for (int hh = 0; hh < 2; ++hh) {
            int r = wm * 32 + mi * 16 + hh * 8 + gr;
            float tot = smRS[r] + smRS[128 + r] + smRS[256 + r] + smRS[384 + r];
            inv[mi][hh] = 1.f / tot;
        }
    bf16* Ob = Og + (size_t)b * CS2 * CC + (size_t)qt * 128 * CC + h * CHD;
    #pragma unroll
    for (int mi = 0; mi < 2; ++mi)
        #pragma unroll
        for (int jj = 0; jj < 5; ++jj)
            #pragma unroll
            for (int hh = 0; hh < 2; ++hh) {
                int row = wm * 32 + mi * 16 + hh * 8 + gr;
                int col = wn * 40 + jj * 8 + q2 * 2;
                __nv_bfloat162 p = __floats2bfloat162_rn(O[mi][jj][2 * hh] * inv[mi][hh],
                                                         O[mi][jj][2 * hh + 1] * inv[mi][hh]);
                *(__nv_bfloat162*)(Ob + (size_t)row * CC + col) = p;
            }
}

// ======================================================================
// launch
// ======================================================================
template<typename T>
static T* symaddr(const void* s) {
    void* p = nullptr;
    cudaGetSymbolAddress(&p, s);
    return (T*)p;
}

extern "C" void kernel_launch(void* const* d_in, const int* in_sizes, int n_in,
                              void* d_out, int out_size)
{
    const float* hs       = (const float*)d_in[0];
    const float* src_mask = (const float*)d_in[1];
    const float* attn_wq  = (const float*)d_in[2];
    const float* attn_wk  = (const float*)d_in[3];
    const float* attn_wv  = (const float*)d_in[4];
    const float* out_w    = (const float*)d_in[5];
    const float* out_b    = (const float*)d_in[6];
    const float* proc_wq  = (const float*)d_in[7];
    const float* proc_wk  = (const float*)d_in[8];
    const float* proc_wv  = (const float*)d_in[9];
    const float* ww       = (const float*)d_in[10];
    const float* wb       = (const float*)d_in[11];
    float* out = (float*)d_out;

    float* W   = symaddr<float>(g_w);
    bf16*  HSB = symaddr<bf16>(g_hsb);
    bf16*  WT  = symaddr<bf16>(g_wT);
    bf16*  Q   = symaddr<bf16>(g_q);
    bf16*  Kb  = symaddr<bf16>(g_k);
    bf16*  Vt  = symaddr<bf16>(g_vt);
    bf16*  AO  = symaddr<bf16>(g_ao);

    const float qsc = (1.0f / sqrtf((float)CHD)) * 1.44269504f;

    cudaFuncSetAttribute(proj_all, cudaFuncAttributeMaxDynamicSharedMemorySize, SMEMB);
    cudaFuncSetAttribute(ogemm,    cudaFuncAttributeMaxDynamicSharedMemorySize, SMEMB);
    cudaFuncSetAttribute(flash,    cudaFuncAttributeMaxDynamicSharedMemorySize, FL_SMEM);

    // 0) fused prep: convert+gate AND weight transposes in one launch
    prep<<<M_ALL + 11200, 256>>>(hs, src_mask, ww, wb,
                                 attn_wq, proc_wq, attn_wk, proc_wk,
                                 attn_wv, proc_wv, out_w,
                                 HSB, W, WT);

    // 1) all projections (fused-gate Q, K, V) in one launch
    proj_all<<<dim3(10, 128), 256, SMEMB>>>(HSB, WT, W, qsc, Q, Kb, Vt);

    // 2) fused attention
    flash<<<dim3(16, 16), 512, FL_SMEM>>>(Q, Kb, Vt, AO);

    // 3) out = attn_out @ out_w + out_b + hidden (fp32)
    ogemm<<<dim3(10, 32), 256, SMEMB>>>(AO, WT + 6 * WSZ_C, out, out_b, hs);
}

// round 17
// speedup vs baseline: 1.0701x; 1.0046x over previous
#include <cuda_runtime.h>
#include <cuda_bf16.h>
#include <cstdint>
#include <math.h>

#define CB 2
#define CS2 2048
#define CS 1024
#define CC 1280
#define CNH 8
#define CHD 160
#define M_ALL 4096
#define HSZ 5242880
#define WSZ_C 1638400

#define STAGES 4
#define STG_B 20480          // bytes per stage (As 10240 + Bs 10240)
#define SMEMB (STAGES * STG_B)   // 81920

// ogemm M-split: 64x128 tile, 128 threads, stage = A 5120 + B 10240
#define OG_STG 15360
#define OG_SMEM (STAGES * OG_STG)   // 61440

// flash smem layout (bytes)
#define FL_SQ 0              // 128x168 bf16 = 43008
#define FL_SK 43008          // 2 x (128x168 bf16) = 86016
#define FL_SV 129024         // 160x136 bf16 = 43520
#define FL_SP 172544         // 128x136 bf16 = 34816
#define FL_RS 207360         // 4x128 f32 = 2048
#define FL_SMEM 209408

typedef __nv_bfloat16 bf16;

// ---- scratch (static device globals: allocation-free) ----
__device__ float g_w[M_ALL];
__device__ bf16  g_hsb[HSZ];
__device__ bf16  g_wT[7 * CC * CC];
__device__ bf16  g_q[HSZ];
__device__ bf16  g_k[HSZ];
__device__ bf16  g_vt[HSZ];              // V transposed: (B, C, S2)
__device__ bf16  g_ao[HSZ];

// ======================================================================
// helpers
// ======================================================================
#define LDSM4(R, addr) \
    asm volatile("ldmatrix.sync.aligned.m8n8.x4.shared.b16 {%0,%1,%2,%3}, [%4];" \
        : "=r"((R)[0]), "=r"((R)[1]), "=r"((R)[2]), "=r"((R)[3]) : "r"(addr))

#define LDSM2(R, addr) \
    asm volatile("ldmatrix.sync.aligned.m8n8.x2.shared.b16 {%0,%1}, [%2];" \
        : "=r"((R)[0]), "=r"((R)[1]) : "r"(addr))

__device__ __forceinline__ void mma16816(float* c, const unsigned* a, unsigned b0, unsigned b1) {
    asm volatile(
        "mma.sync.aligned.m16n8k16.row.col.f32.bf16.bf16.f32 "
        "{%0,%1,%2,%3}, {%4,%5,%6,%7}, {%8,%9}, {%0,%1,%2,%3};"
        : "+f"(c[0]), "+f"(c[1]), "+f"(c[2]), "+f"(c[3])
        : "r"(a[0]), "r"(a[1]), "r"(a[2]), "r"(a[3]), "r"(b0), "r"(b1));
}

__device__ __forceinline__ void cpa(unsigned d, const bf16* s, int szb) {
    asm volatile("cp.async.cg.shared.global [%0], [%1], 16, %2;" :: "r"(d), "l"(s), "r"(szb));
}
__device__ __forceinline__ void cpcommit() { asm volatile("cp.async.commit_group;"); }
__device__ __forceinline__ void cpwait()   { asm volatile("cp.async.wait_group %0;" :: "n"(STAGES - 2)); }
__device__ __forceinline__ void cpwait1()  { asm volatile("cp.async.wait_group 1;" ::: "memory"); }

__device__ __forceinline__ float ex2f(float x) {
    float y; asm("ex2.approx.f32 %0, %1;" : "=f"(y) : "f"(x)); return y;
}

// ======================================================================
// prep: fused (hs fp32->bf16 + gate dot) AND weight transpose, one launch.
// ======================================================================
__global__ __launch_bounds__(256) void prep(
    const float* __restrict__ hs, const float* __restrict__ mask,
    const float* __restrict__ ww, const float* __restrict__ wb,
    const float* w0, const float* w1, const float* w2, const float* w3,
    const float* w4, const float* w5, const float* w6,
    bf16* __restrict__ hsb, float* __restrict__ wout, bf16* __restrict__ wT)
{
    __shared__ float t[32][33];
    const int z = blockIdx.x;
    const int tid = threadIdx.x;

    if (z < M_ALL) {
        const float2* h2 = (const float2*)(hs + (size_t)z * CC);
        const float2* w2p = (const float2*)ww;
        __nv_bfloat162* o2 = (__nv_bfloat162*)(hsb + (size_t)z * CC);
        float acc = 0.f;
        for (int i = tid; i < 640; i += 256) {
            float2 v = h2[i];
            float2 w = w2p[i];
            acc += v.x * w.x + v.y * w.y;
            o2[i] = __floats2bfloat162_rn(v.x, v.y);
        }
        #pragma unroll
        for (int o = 16; o; o >>= 1) acc += __shfl_xor_sync(0xffffffffu, acc, o);
        if ((tid & 31) == 0) t[0][tid >> 5] = acc;
        __syncthreads();
        if (tid == 0) {
            float tot = 0.f;
            #pragma unroll
            for (int i = 0; i < 8; ++i) tot += t[0][i];
            int b = z / CS2;
            int s = (z % CS2) % CS;
            float mval = mask[(size_t)b * 65536 + (size_t)(s / 32) * 8 * 256 + (size_t)(s % 32) * 8];
            float x = tot + mval * ww[CC] + wb[0];
            wout[z] = 1.f / (1.f + expf(-x));
        }
        return;
    }

    const float* srcs[7] = {w0, w1, w2, w3, w4, w5, w6};
    int idx = z - M_ALL;
    int wz = idx / 1600;
    int r  = idx - wz * 1600;
    int by = r / 40, bx = r - by * 40;
    const float* src = srcs[wz];
    bf16* dst = wT + (size_t)wz * CC * CC;
    int tx = tid & 31, ty = tid >> 5;
    int x0 = bx * 32, y0 = by * 32;
    #pragma unroll
    for (int j = 0; j < 4; ++j)
        t[ty + j * 8][tx] = src[(size_t)(y0 + ty + j * 8) * CC + x0 + tx];
    __syncthreads();
    #pragma unroll
    for (int j = 0; j < 4; ++j)
        dst[(size_t)(x0 + ty + j * 8) * CC + y0 + tx] =
            __float2bfloat16(t[tx][ty + j * 8]);
}

// ======================================================================
// R8-proven 4-stage k=32 pipeline core (single B, 128x128 tile).
// ======================================================================
struct GemmAcc { float a[2][8][4]; };

__device__ __forceinline__ void gemm_core(
    const bf16* pA, const bf16* pB, unsigned sbase, int tid, GemmAcc& R)
{
    const int warp = tid >> 5, lane = tid & 31;
    const int wm = warp >> 1, wn = warp & 1;
    const int row = tid >> 1;
    const int col = (tid & 1) << 4;

    unsigned dA = sbase + (unsigned)((row * 40 + col) * 2);
    unsigned dB = dA + 10240;

    #pragma unroll
    for (int i = 0; i < 2; ++i)
        #pragma unroll
        for (int j = 0; j < 8; ++j)
            #pragma unroll
            for (int k = 0; k < 4; ++k) R.a[i][j][k] = 0.f;

    #pragma unroll
    for (int s = 0; s < STAGES - 1; ++s) {
        unsigned o = s * STG_B;
        cpa(dA + o,      pA + s * 32,      16);
        cpa(dA + o + 16, pA + s * 32 + 8,  16);
        cpa(dB + o,      pB + s * 32,      16);
        cpa(dB + o + 16, pB + s * 32 + 8,  16);
        cpcommit();
    }
    cpwait();
    __syncthreads();

    const int g = lane >> 3, lr = lane & 7;
    unsigned aAddr = sbase + (unsigned)(((wm * 32 + (g & 1) * 8 + lr) * 40 + (g >> 1) * 8) * 2);
    unsigned bAddr = sbase + 10240u + (unsigned)(((wn * 64 + (g >> 1) * 8 + lr) * 40 + (g & 1) * 8) * 2);

    const int ktiles = 40;
    for (int t = 0; t < ktiles; ++t) {
        int nt = t + STAGES - 1;
        if (nt < ktiles) {
            unsigned o = (nt & (STAGES - 1)) * STG_B;
            cpa(dA + o,      pA + nt * 32,      16);
            cpa(dA + o + 16, pA + nt * 32 + 8,  16);
            cpa(dB + o,      pB + nt * 32,      16);
            cpa(dB + o + 16, pB + nt * 32 + 8,  16);
        }
        cpcommit();

        unsigned o = (t & (STAGES - 1)) * STG_B;
        #pragma unroll
        for (int kk = 0; kk < 2; ++kk) {
            unsigned a0[4], a1[4];
            LDSM4(a0, aAddr + o + kk * 32);
            LDSM4(a1, aAddr + o + 1280 + kk * 32);
            #pragma unroll
            for (int jj = 0; jj < 4; ++jj) {
                unsigned b[4];
                LDSM4(b, bAddr + o + jj * 1280 + kk * 32);
                mma16816(R.a[0][2 * jj],     a0, b[0], b[1]);
                mma16816(R.a[1][2 * jj],     a1, b[0], b[1]);
                mma16816(R.a[0][2 * jj + 1], a0, b[2], b[3]);
                mma16816(R.a[1][2 * jj + 1], a1, b[2], b[3]);
            }
        }
        cpwait();
        __syncthreads();
    }
}

// ======================================================================
// Dual-B core: tile 128x64, computes A@Wq and A@Wp simultaneously.
// ======================================================================
__device__ __forceinline__ void gemm_core_dual(
    const bf16* pA, const bf16* pB, unsigned sbase, int tid,
    float Rq[2][4][4], float Rp[2][4][4])
{
    const int warp = tid >> 5, lane = tid & 31;
    const int wm = warp >> 1, wn = warp & 1;
    const int row = tid >> 1;
    const int col = (tid & 1) << 4;

    unsigned dA = sbase + (unsigned)((row * 40 + col) * 2);
    unsigned dB = dA + 10240;

    #pragma unroll
    for (int i = 0; i < 2; ++i)
        #pragma unroll
        for (int j = 0; j < 4; ++j)
            #pragma unroll
            for (int k = 0; k < 4; ++k) { Rq[i][j][k] = 0.f; Rp[i][j][k] = 0.f; }

    #pragma unroll
    for (int s = 0; s < STAGES - 1; ++s) {
        unsigned o = s * STG_B;
        cpa(dA + o,      pA + s * 32,      16);
        cpa(dA + o + 16, pA + s * 32 + 8,  16);
        cpa(dB + o,      pB + s * 32,      16);
        cpa(dB + o + 16, pB + s * 32 + 8,  16);
        cpcommit();
    }
    cpwait();
    __syncthreads();

    const int g = lane >> 3, lr = lane & 7;
    unsigned aAddr = sbase + (unsigned)(((wm * 32 + (g & 1) * 8 + lr) * 40 + (g >> 1) * 8) * 2);
    unsigned bAddrQ = sbase + 10240u + (unsigned)(((wn * 32 + (g >> 1) * 8 + lr) * 40 + (g & 1) * 8) * 2);
    unsigned bAddrP = bAddrQ + 64u * 80u;

    const int ktiles = 40;
    for (int t = 0; t < ktiles; ++t) {
        int nt = t + STAGES - 1;
        if (nt < ktiles) {
            unsigned o = (nt & (STAGES - 1)) * STG_B;
            cpa(dA + o,      pA + nt * 32,      16);
            cpa(dA + o + 16, pA + nt * 32 + 8,  16);
            cpa(dB + o,      pB + nt * 32,      16);
            cpa(dB + o + 16, pB + nt * 32 + 8,  16);
        }
        cpcommit();

        unsigned o = (t & (STAGES - 1)) * STG_B;
        #pragma unroll
        for (int kk = 0; kk < 2; ++kk) {
            unsigned a0[4], a1[4];
            LDSM4(a0, aAddr + o + kk * 32);
            LDSM4(a1, aAddr + o + 1280 + kk * 32);
            #pragma unroll
            for (int jj = 0; jj < 2; ++jj) {
                unsigned b[4];
                LDSM4(b, bAddrQ + o + jj * 1280 + kk * 32);
                mma16816(Rq[0][2 * jj],     a0, b[0], b[1]);
                mma16816(Rq[1][2 * jj],     a1, b[0], b[1]);
                mma16816(Rq[0][2 * jj + 1], a0, b[2], b[3]);
                mma16816(Rq[1][2 * jj + 1], a1, b[2], b[3]);
                LDSM4(b, bAddrP + o + jj * 1280 + kk * 32);
                mma16816(Rp[0][2 * jj],     a0, b[0], b[1]);
                mma16816(Rp[1][2 * jj],     a1, b[0], b[1]);
                mma16816(Rp[0][2 * jj + 1], a0, b[2], b[3]);
                mma16816(Rp[1][2 * jj + 1], a1, b[2], b[3]);
            }
        }
        cpwait();
        __syncthreads();
    }
}

// ======================================================================
// Merged projection kernel: y<64 dual-Q (128x64, fused gate), else K/V.
// grid (10, 128). (unchanged, proven)
// ======================================================================
__global__ __launch_bounds__(256, 2) void proj_all(
    const bf16* __restrict__ HSB, const bf16* __restrict__ WT,
    const float* __restrict__ W, float qsc,
    bf16* __restrict__ Qo, bf16* __restrict__ Kb, bf16* __restrict__ Vt)
{
    extern __shared__ __align__(16) bf16 smg[];
    const int y = blockIdx.y;
    const int tid = threadIdx.x;
    const int warp = tid >> 5, lane = tid & 31;
    const int wm = warp >> 1, wn = warp & 1;
    const int gr = lane >> 2, gc = (lane & 3) * 2;
    unsigned sbase = (unsigned)__cvta_generic_to_shared(smg);

    if (y < 64) {
        int my = y >> 1;
        int n0 = ((y & 1) * 10 + blockIdx.x) * 64;
        const bf16* A = HSB + (size_t)my * 128 * CC;
        const int row = tid >> 1;
        const bf16* pA = A + (size_t)row * CC + ((tid & 1) << 4);
        const bf16* pB;
        if (row < 64) pB = WT + (size_t)(n0 + row) * CC + ((tid & 1) << 4);
        else          pB = WT + WSZ_C + (size_t)(n0 + row - 64) * CC + ((tid & 1) << 4);

        float Rq[2][4][4], Rp[2][4][4];
        gemm_core_dual(pA, pB, sbase, tid, Rq, Rp);

        bf16* C = Qo + (size_t)my * 128 * CC;
        #pragma unroll
        for (int mi = 0; mi < 2; ++mi)
            #pragma unroll
            for (int hh = 0; hh < 2; ++hh) {
                int m = wm * 32 + mi * 16 + gr + hh * 8;
                float wv = W[my * 128 + m];
                float iw = 1.f - wv;
                #pragma unroll
                for (int jj = 0; jj < 4; ++jj) {
                    int n = n0 + wn * 32 + jj * 8 + gc;
                    float v0 = (Rq[mi][jj][2 * hh]     * wv + Rp[mi][jj][2 * hh]     * iw) * qsc;
                    float v1 = (Rq[mi][jj][2 * hh + 1] * wv + Rp[mi][jj][2 * hh + 1] * iw) * qsc;
                    *(__nv_bfloat162*)(C + (size_t)m * CC + n) = __floats2bfloat162_rn(v0, v1);
                }
            }
        return;
    }

    const bf16* A;
    const bf16* B;
    bf16* C;
    int ldc;
    bool transo = false;
    {
        int u = y & 31;
        int bh = u >> 3, my = u & 7;
        int b = bh >> 1, half = bh & 1;
        A = HSB + (size_t)b * (CS2 * CC) + (size_t)half * CS * CC + (size_t)my * 128 * CC;
        if (y < 96) {
            B = WT + (size_t)(2 + half) * WSZ_C;
            C = Kb + (size_t)b * (CS2 * CC) + (size_t)half * CS * CC + (size_t)my * 128 * CC;
            ldc = CC;
        } else {
            B = WT + (size_t)(4 + half) * WSZ_C;
            C = Vt + (size_t)b * (CC * CS2) + (size_t)half * CS + (size_t)my * 128;
            ldc = CS2;
            transo = true;
        }
    }

    const int n0 = blockIdx.x * 128;
    const bf16* pA = A + (size_t)(tid >> 1) * CC + ((tid & 1) << 4);
    const bf16* pB = B + (size_t)(n0 + (tid >> 1)) * CC + ((tid & 1) << 4);

    GemmAcc R;
    gemm_core(pA, pB, sbase, tid, R);

    if (!transo) {
        #pragma unroll
        for (int mi = 0; mi < 2; ++mi)
            #pragma unroll
            for (int jj = 0; jj < 8; ++jj) {
                int n = n0 + wn * 64 + jj * 8 + gc;
                #pragma unroll
                for (int h = 0; h < 2; ++h) {
                    int m = wm * 32 + mi * 16 + gr + h * 8;
                    __nv_bfloat162 p = __floats2bfloat162_rn(R.a[mi][jj][2 * h],
                                                             R.a[mi][jj][2 * h + 1]);
                    *(__nv_bfloat162*)(C + (size_t)m * ldc + n) = p;
                }
            }
    } else {
        #pragma unroll
        for (int mi = 0; mi < 2; ++mi)
            #pragma unroll
            for (int jj = 0; jj < 8; ++jj) {
                int n = n0 + wn * 64 + jj * 8 + gc;
                #pragma unroll
                for (int h = 0; h < 2; ++h) {
                    int m = wm * 32 + mi * 16 + gr + h * 8;
                    C[(size_t)n * ldc + m]       = __float2bfloat16(R.a[mi][jj][2 * h]);
                    C[(size_t)(n + 1) * ldc + m] = __float2bfloat16(R.a[mi][jj][2 * h + 1]);
                }
            }
    }
}

// ======================================================================
// out-projection GEMM, M-split: 64x128 tile, 128 threads (4 warps, 2m x 2n,
// warp tile 32x64 = identical mix to gemm_core). 3 CTAs/SM. grid (10, 64).
// ======================================================================
__global__ __launch_bounds__(128, 3) void ogemm(
    const bf16* __restrict__ A, const bf16* __restrict__ B, float* __restrict__ Cf,
    const float* __restrict__ bias, const float* __restrict__ resid)
{
    extern __shared__ __align__(16) bf16 smg[];
    const int tid = threadIdx.x;
    const int m0 = blockIdx.y * 64, n0 = blockIdx.x * 128;
    const int warp = tid >> 5, lane = tid & 31;
    const int wm = warp >> 1, wn = warp & 1;
    const int row = tid >> 1;            // 0..63
    const int col = (tid & 1) << 4;

    const bf16* pA  = A + (size_t)(m0 + row) * CC + col;
    const bf16* pB0 = B + (size_t)(n0 + row) * CC + col;
    const bf16* pB1 = B + (size_t)(n0 + row + 64) * CC + col;

    unsigned sbase = (unsigned)__cvta_generic_to_shared(smg);
    unsigned dA  = sbase + (unsigned)((row * 40 + col) * 2);
    unsigned dB0 = sbase + 5120u + (unsigned)((row * 40 + col) * 2);
    unsigned dB1 = dB0 + 5120u;

    float acc[2][8][4];
    #pragma unroll
    for (int i = 0; i < 2; ++i)
        #pragma unroll
        for (int j = 0; j < 8; ++j)
            #pragma unroll
            for (int k = 0; k < 4; ++k) acc[i][j][k] = 0.f;

    #pragma unroll
    for (int s = 0; s < STAGES - 1; ++s) {
        unsigned o = s * OG_STG;
        cpa(dA + o,       pA  + s * 32,      16);
        cpa(dA + o + 16,  pA  + s * 32 + 8,  16);
        cpa(dB0 + o,      pB0 + s * 32,      16);
        cpa(dB0 + o + 16, pB0 + s * 32 + 8,  16);
        cpa(dB1 + o,      pB1 + s * 32,      16);
        cpa(dB1 + o + 16, pB1 + s * 32 + 8,  16);
        cpcommit();
    }
    cpwait();
    __syncthreads();

    const int g = lane >> 3, lr = lane & 7;
    unsigned aAddr = sbase + (unsigned)(((wm * 32 + (g & 1) * 8 + lr) * 40 + (g >> 1) * 8) * 2);
    unsigned bAddr = sbase + 5120u + (unsigned)(((wn * 64 + (g >> 1) * 8 + lr) * 40 + (g & 1) * 8) * 2);

    const int ktiles = 40;
    for (int t = 0; t < ktiles; ++t) {
        int nt = t + STAGES - 1;
        if (nt < ktiles) {
            unsigned o = (nt & (STAGES - 1)) * OG_STG;
            cpa(dA + o,       pA  + nt * 32,      16);
            cpa(dA + o + 16,  pA  + nt * 32 + 8,  16);
            cpa(dB0 + o,      pB0 + nt * 32,      16);
            cpa(dB0 + o + 16, pB0 + nt * 32 + 8,  16);
            cpa(dB1 + o,      pB1 + nt * 32,      16);
            cpa(dB1 + o + 16, pB1 + nt * 32 + 8,  16);
        }
        cpcommit();

        unsigned o = (t & (STAGES - 1)) * OG_STG;
        #pragma unroll
        for (int kk = 0; kk < 2; ++kk) {
            unsigned a0[4], a1[4];
            LDSM4(a0, aAddr + o + kk * 32);
            LDSM4(a1, aAddr + o + 1280 + kk * 32);
            #pragma unroll
            for (int jj = 0; jj < 4; ++jj) {
                unsigned b[4];
                LDSM4(b, bAddr + o + jj * 1280 + kk * 32);
                mma16816(acc[0][2 * jj],     a0, b[0], b[1]);
                mma16816(acc[1][2 * jj],     a1, b[0], b[1]);
                mma16816(acc[0][2 * jj + 1], a0, b[2], b[3]);
                mma16816(acc[1][2 * jj + 1], a1, b[2], b[3]);
            }
        }
        cpwait();
        __syncthreads();
    }

    const int gr = lane >> 2, gc = (lane & 3) * 2;
    #pragma unroll
    for (int mi = 0; mi < 2; ++mi)
        #pragma unroll
        for (int jj = 0; jj < 8; ++jj) {
            int n = n0 + wn * 64 + jj * 8 + gc;
            #pragma unroll
            for (int h = 0; h < 2; ++h) {
                int m = m0 + wm * 32 + mi * 16 + gr + h * 8;
                float v0 = acc[mi][jj][2 * h]     + bias[n]     + resid[(size_t)m * CC + n];
                float v1 = acc[mi][jj][2 * h + 1] + bias[n + 1] + resid[(size_t)m * CC + n + 1];
                *(float2*)(Cf + (size_t)m * CC + n) = make_float2(v0, v1);
            }
        }
}

// ======================================================================
// Fused flash attention, static-max variant (R8, known good).
// ======================================================================
__global__ __launch_bounds__(512, 1) void flash(
    const bf16* __restrict__ Qg, const bf16* __restrict__ Kg,
    const bf16* __restrict__ Vg, bf16* __restrict__ Og)
{
    extern __shared__ __align__(16) char sm[];
    unsigned sb = (unsigned)__cvta_generic_to_shared(sm);
    const int tid = threadIdx.x;
    const int warp = tid >> 5, lane = tid & 31;
    const int wm = warp >> 2, wn = warp & 3;
    const int g = lane >> 3, lr = lane & 7;
    const int q2 = lane & 3, gr = lane >> 2;
    const int b = blockIdx.y >> 3, h = blockIdx.y & 7;
    const int qt = blockIdx.x;

    const bf16* Qp = Qg + (size_t)b * CS2 * CC + (size_t)qt * 128 * CC + h * CHD;
    const bf16* Kp = Kg + (size_t)b * CS2 * CC + h * CHD;
    const bf16* Vp = Vg + (size_t)b * CC * CS2 + (size_t)h * CHD * CS2;

    #pragma unroll
    for (int i = 0; i < 5; ++i) {
        int c = tid + (i << 9); int row = c / 20, c16 = c % 20;
        cpa(sb + FL_SQ + row * 336 + c16 * 16, Qp + (size_t)row * CC + c16 * 8, 16);
    }
    cpcommit();
    #pragma unroll
    for (int i = 0; i < 5; ++i) {
        int c = tid + (i << 9); int row = c / 20, c16 = c % 20;
        cpa(sb + FL_SK + row * 336 + c16 * 16, Kp + (size_t)row * CC + c16 * 8, 16);
    }
    cpcommit();
    #pragma unroll
    for (int i = 0; i < 5; ++i) {
        int c = tid + (i << 9); int row = c / 16, c16 = c % 16;
        cpa(sb + FL_SV + row * 272 + c16 * 16, Vp + (size_t)row * CS2 + c16 * 8, 16);
    }
    cpcommit();

    float O[2][5][4];
    #pragma unroll
    for (int i = 0; i < 2; ++i)
        #pragma unroll
        for (int j = 0; j < 5; ++j)
            #pragma unroll
            for (int k = 0; k < 4; ++k) O[i][j][k] = 0.f;
    float lsum[2][2] = {{0.f, 0.f}, {0.f, 0.f}};

    unsigned aQ  = sb + FL_SQ + (unsigned)(((wm * 32 + (g & 1) * 8 + lr) * 168 + (g >> 1) * 8) * 2);
    unsigned aP  = sb + FL_SP + (unsigned)(((wm * 32 + (g & 1) * 8 + lr) * 136 + (g >> 1) * 8) * 2);
    unsigned bVa = sb + FL_SV + (unsigned)(((wn * 40 + (g >> 1) * 8 + lr) * 136 + (g & 1) * 8) * 2);
    unsigned bV2 = sb + FL_SV + (unsigned)(((wn * 40 + 32 + lr) * 136 + ((lane >> 3) & 1) * 8) * 2);
    unsigned bKl = sb + FL_SK + (unsigned)(((wn * 32 + (g >> 1) * 8 + lr) * 168 + (g & 1) * 8) * 2);

    bf16* sPp = (bf16*)(sm + FL_SP);

    for (int t = 0; t < 16; ++t) {
        cpwait1();
        __syncthreads();
        if (t < 15) {
            unsigned kb = sb + FL_SK + (unsigned)(((t + 1) & 1) * 43008);
            const bf16* src = Kp + (size_t)(t + 1) * 128 * CC;
            #pragma unroll
            for (int i = 0; i < 5; ++i) {
                int c = tid + (i << 9); int row = c / 20, c16 = c % 20;
                cpa(kb + row * 336 + c16 * 16, src + (size_t)row * CC + c16 * 8, 16);
            }
        }
        cpcommit();

        float S[2][4][4];
        #pragma unroll
        for (int i = 0; i < 2; ++i)
            #pragma unroll
            for (int j = 0; j < 4; ++j)
                #pragma unroll
                for (int k = 0; k < 4; ++k) S[i][j][k] = 0.f;
        unsigned bK = bKl + (unsigned)((t & 1) * 43008);
        #pragma unroll
        for (int kk = 0; kk < 10; ++kk) {
            unsigned a0[4], a1[4], bb[4];
            LDSM4(a0, aQ + kk * 32);
            LDSM4(a1, aQ + kk * 32 + 5376);
            LDSM4(bb, bK + kk * 32);
            mma16816(S[0][0], a0, bb[0], bb[1]);
            mma16816(S[0][1], a0, bb[2], bb[3]);
            mma16816(S[1][0], a1, bb[0], bb[1]);
            mma16816(S[1][1], a1, bb[2], bb[3]);
            LDSM4(bb, bK + kk * 32 + 5376);
            mma16816(S[0][2], a0, bb[0], bb[1]);
            mma16816(S[0][3], a0, bb[2], bb[3]);
            mma16816(S[1][2], a1, bb[0], bb[1]);
            mma16816(S[1][3], a1, bb[2], bb[3]);
        }

        #pragma unroll
        for (int mi = 0; mi < 2; ++mi)
            #pragma unroll
            for (int jj = 0; jj < 4; ++jj)
                #pragma unroll
                for (int hh = 0; hh < 2; ++hh) {
                    float p0 = ex2f(S[mi][jj][2 * hh]);
                    float p1 = ex2f(S[mi][jj][2 * hh + 1]);
                    lsum[mi][hh] += p0 + p1;
                    int prow = wm * 32 + mi * 16 + hh * 8 + gr;
                    int pcol = wn * 32 + jj * 8 + q2 * 2;
                    *(__nv_bfloat162*)(sPp + prow * 136 + pcol) = __floats2bfloat162_rn(p0, p1);
                }

        cpwait1();
        __syncthreads();

        #pragma unroll
        for (int kk = 0; kk < 8; ++kk) {
            unsigned a0[4], a1[4], bb[4], b2[2];
            LDSM4(a0, aP + kk * 32);
            LDSM4(a1, aP + kk * 32 + 4352);
            LDSM4(bb, bVa + kk * 32);
            mma16816(O[0][0], a0, bb[0], bb[1]);
            mma16816(O[0][1], a0, bb[2], bb[3]);
            mma16816(O[1][0], a1, bb[0], bb[1]);
            mma16816(O[1][1], a1, bb[2], bb[3]);
            LDSM4(bb, bVa + kk * 32 + 4352);
            mma16816(O[0][2], a0, bb[0], bb[1]);
            mma16816(O[0][3], a0, bb[2], bb[3]);
            mma16816(O[1][2], a1, bb[0], bb[1]);
            mma16816(O[1][3], a1, bb[2], bb[3]);
            LDSM2(b2, bV2 + kk * 32);
            mma16816(O[0][4], a0, b2[0], b2[1]);
            mma16816(O[1][4], a1, b2[0], b2[1]);
        }
        __syncthreads();
        if (t < 15) {
            const bf16* src = Vp + (size_t)(t + 1) * 128;
            #pragma unroll
            for (int i = 0; i < 5; ++i) {
                int c = tid + (i << 9); int row = c / 16, c16 = c % 16;
                cpa(sb + FL_SV + row * 272 + c16 * 16, src + (size_t)row * CS2 + c16 * 8, 16);
            }
            cpcommit();
        }
    }

    float* smRS = (float*)(sm + FL_RS);
    #pragma unroll
    for (int mi = 0; mi < 2; ++mi)
        #pragma unroll
        for (int hh = 0; hh < 2; ++hh) {
            float s = lsum[mi][hh];
            s += __shfl_xor_sync(0xffffffffu, s, 1);
            s += __shfl_xor_sync(0xffffffffu, s, 2);
            if (q2 == 0) smRS[wn * 128 + wm * 32 + mi * 16 + hh * 8 + gr] = s;
        }
    __syncthreads();
    float inv[2][2];
    #pragma unroll
    for (int mi = 0; mi < 2; ++mi)
        #pragma unroll
        for (int hh = 0; hh < 2; ++hh) {
            int r = wm * 32 + mi * 16 + hh * 8 + gr;
            float tot = smRS[r] + smRS[128 + r] + smRS[256 + r] + smRS[384 + r];
            inv[mi][hh] = 1.f / tot;
        }
    bf16* Ob = Og + (size_t)b * CS2 * CC + (size_t)qt * 128 * CC + h * CHD;
    #pragma unroll
    for (int mi = 0; mi < 2; ++mi)
        #pragma unroll
        for (int jj = 0; jj < 5; ++jj)
            #pragma unroll
            for (int hh = 0; hh < 2; ++hh) {
                int row = wm * 32 + mi * 16 + hh * 8 + gr;
                int col = wn * 40 + jj * 8 + q2 * 2;
                __nv_bfloat162 p = __floats2bfloat162_rn(O[mi][jj][2 * hh] * inv[mi][hh],
                                                         O[mi][jj][2 * hh + 1] * inv[mi][hh]);
                *(__nv_bfloat162*)(Ob + (size_t)row * CC + col) = p;
            }
}

// ======================================================================
// launch
// ======================================================================
template<typename T>
static T* symaddr(const void* s) {
    void* p = nullptr;
    cudaGetSymbolAddress(&p, s);
    return (T*)p;
}

extern "C" void kernel_launch(void* const* d_in, const int* in_sizes, int n_in,
                              void* d_out, int out_size)
{
    const float* hs       = (const float*)d_in[0];
    const float* src_mask = (const float*)d_in[1];
    const float* attn_wq  = (const float*)d_in[2];
    const float* attn_wk  = (const float*)d_in[3];
    const float* attn_wv  = (const float*)d_in[4];
    const float* out_w    = (const float*)d_in[5];
    const float* out_b    = (const float*)d_in[6];
    const float* proc_wq  = (const float*)d_in[7];
    const float* proc_wk  = (const float*)d_in[8];
    const float* proc_wv  = (const float*)d_in[9];
    const float* ww       = (const float*)d_in[10];
    const float* wb       = (const float*)d_in[11];
    float* out = (float*)d_out;

    float* W   = symaddr<float>(g_w);
    bf16*  HSB = symaddr<bf16>(g_hsb);
    bf16*  WT  = symaddr<bf16>(g_wT);
    bf16*  Q   = symaddr<bf16>(g_q);
    bf16*  Kb  = symaddr<bf16>(g_k);
    bf16*  Vt  = symaddr<bf16>(g_vt);
    bf16*  AO  = symaddr<bf16>(g_ao);

    const float qsc = (1.0f / sqrtf((float)CHD)) * 1.44269504f;

    cudaFuncSetAttribute(proj_all, cudaFuncAttributeMaxDynamicSharedMemorySize, SMEMB);
    cudaFuncSetAttribute(ogemm,    cudaFuncAttributeMaxDynamicSharedMemorySize, OG_SMEM);
    cudaFuncSetAttribute(flash,    cudaFuncAttributeMaxDynamicSharedMemorySize, FL_SMEM);

    // 0) fused prep: convert+gate AND weight transposes in one launch
    prep<<<M_ALL + 11200, 256>>>(hs, src_mask, ww, wb,
                                 attn_wq, proc_wq, attn_wk, proc_wk,
                                 attn_wv, proc_wv, out_w,
                                 HSB, W, WT);

    // 1) all projections (fused-gate Q, K, V) in one launch
    proj_all<<<dim3(10, 128), 256, SMEMB>>>(HSB, WT, W, qsc, Q, Kb, Vt);

    // 2) fused attention
    flash<<<dim3(16, 16), 512, FL_SMEM>>>(Q, Kb, Vt, AO);

    // 3) out = attn_out @ out_w + out_b + hidden, M-split 64x128 tiles
    ogemm<<<dim3(10, 64), 128, OG_SMEM>>>(AO, WT + 6 * WSZ_C, out, out_b, hs);
}